// round 4
// baseline (speedup 1.0000x reference)
#include <cuda_runtime.h>

typedef unsigned long long ull;

// ---------------------------------------------------------------------------
// B=2048 trees, N=128 nodes, M=127 conv positions.
// Channels: 128 -> 256 -> 128 -> 64, then FC 64->32->1.
// Activations live in smem TRANSPOSED: act[pos][C] with padded pitch, so the
// gather for one position reads 4 consecutive channels via one LDS.128.
// Thread map: tm = tid>>4 (position group), to = tid&15 (o lane) so that each
// half-warp broadcasts its gather loads (conflict-free).
// ---------------------------------------------------------------------------

// Transposed weights in gmem: Wt[(k*C + c)*O + o] = W[o][c][3] -> [k][c][o]
__device__ float g_Wt1[3 * 128 * 256];
__device__ float g_Wt2[3 * 256 * 128];
__device__ float g_Wt3[3 * 128 * 64];

struct SmemT {
    float bufA[128 * 260];   // 133,120 B : [pos][260] (C/O up to 256, pad 4)
    float bufB[128 * 132];   //  67,584 B : [pos][132] (C/O = 128, pad 4)
    ull   wbuf[16 * 128];    //  16,384 B : staged dup weights (16 s-rows)
    int   idx[384];
    float red[80];
};

__device__ __forceinline__ ull pk(float lo, float hi) {
    ull r;
    asm("mov.b64 %0, {%1,%2};" : "=l"(r) : "f"(lo), "f"(hi));
    return r;
}
__device__ __forceinline__ void unpk(ull x, float& lo, float& hi) {
    asm("mov.b64 {%0,%1}, %2;" : "=f"(lo), "=f"(hi) : "l"(x));
}
// packed fp32x2 FMA: d = a*b + d (lanewise)
__device__ __forceinline__ void ffma2(ull& d, ull a, ull b) {
    asm("fma.rn.f32x2 %0, %1, %2, %0;" : "+l"(d) : "l"(a), "l"(b));
}

// ---------------------------------------------------------------------------
// One tree-conv layer + per-tree LayerNorm (+ optional leaky ReLU).
//   act_in  : [128][CP] smem, valid cols [0,C)
//   act_out : [128][OP] smem, valid cols [0,O)
//   Wt      : gmem, [(k*C+c)*O + o]
//   I       : per-thread gather row indices I[k*8+j] for positions p = tm*8+j
// ---------------------------------------------------------------------------
template <int C, int CP, int O, int OP, bool LEAKY>
__device__ void layer(const float* __restrict__ act_in,
                      float* __restrict__ act_out,
                      const float* __restrict__ Wt,
                      const float* __restrict__ bias,
                      SmemT* sm, int tid, const int* I)
{
    constexpr int OT = (O >= 128) ? 128 : O;   // o-tile per pass
    constexpr int RO = OT / 16;                // o's per thread (8 or 4)
    constexpr int PASSES = O / OT;

    const int tm = tid >> 4;
    const int to = tid & 15;

    float lsum = 0.f, lsq = 0.f;

    for (int pass = 0; pass < PASSES; ++pass) {
        const int o_base = pass * OT;

        ull acc[RO][4];
#pragma unroll
        for (int r = 0; r < RO; ++r)
#pragma unroll
            for (int j2 = 0; j2 < 4; ++j2) acc[r][j2] = 0ull;

#pragma unroll
        for (int k = 0; k < 3; ++k) {
            int aoff[8];                       // gather row offsets (floats)
#pragma unroll
            for (int j = 0; j < 8; ++j) aoff[j] = I[k * 8 + j] * CP;

            for (int cb = 0; cb < C; cb += 16) {
                __syncthreads();
                // ---- stage 16 weight rows, duplicated (w,w), interleaved:
                // ull index = (s>>1)*(2*OT) + o*2 + (s&1)
                {
                    constexpr int NU = 16 * OT;
#pragma unroll
                    for (int i = 0; i < NU / 256; ++i) {
                        int e = i * 256 + tid;
                        int s = e / OT, o = e % OT;
                        float f = Wt[(k * C + cb + s) * O + o_base + o];
                        sm->wbuf[(s >> 1) * (2 * OT) + o * 2 + (s & 1)] = pk(f, f);
                    }
                }
                __syncthreads();

                // ---- 16 reduction steps, in 4 groups of 4 channels ----
#pragma unroll
                for (int sg = 0; sg < 4; ++sg) {
                    float4 v4[8];
#pragma unroll
                    for (int j = 0; j < 8; ++j)
                        v4[j] = *(const float4*)(act_in + aoff[j] + cb + sg * 4);

#pragma unroll
                    for (int s2 = 0; s2 < 2; ++s2) {
                        // weight pairs for s = sg*4 + 2*s2 (even) and +1 (odd)
                        const ulonglong2* w2 =
                            ((const ulonglong2*)sm->wbuf) + (sg * 2 + s2) * OT + to;
                        ull we[RO], wo[RO];
#pragma unroll
                        for (int r = 0; r < RO; ++r) {
                            ulonglong2 t = w2[r * 16];
                            we[r] = t.x; wo[r] = t.y;
                        }

                        ull vpe[4], vpo[4];
#pragma unroll
                        for (int j2 = 0; j2 < 4; ++j2) {
                            const float* a0 = (const float*)&v4[2 * j2];
                            const float* a1 = (const float*)&v4[2 * j2 + 1];
                            vpe[j2] = pk(a0[2 * s2],     a1[2 * s2]);
                            vpo[j2] = pk(a0[2 * s2 + 1], a1[2 * s2 + 1]);
                        }

#pragma unroll
                        for (int r = 0; r < RO; ++r)
#pragma unroll
                            for (int j2 = 0; j2 < 4; ++j2)
                                ffma2(acc[r][j2], we[r], vpe[j2]);
#pragma unroll
                        for (int r = 0; r < RO; ++r)
#pragma unroll
                            for (int j2 = 0; j2 < 4; ++j2)
                                ffma2(acc[r][j2], wo[r], vpo[j2]);
                    }
                }
            }
        }

        // ---- epilogue: +bias, zero slot 0, write [pos][o], LN stats ----
#pragma unroll
        for (int r = 0; r < RO; ++r) {
            const int o = o_base + to + r * 16;     // interleaved o mapping
            const float bo = bias[o];
#pragma unroll
            for (int j2 = 0; j2 < 4; ++j2) {
                float x0, x1;
                unpk(acc[r][j2], x0, x1);
                const int p0 = tm * 8 + 2 * j2;
                float y0 = (p0 == 0) ? 0.f : (x0 + bo);
                float y1 = x1 + bo;                 // p0+1 never 0
                act_out[p0 * OP + o]       = y0;
                act_out[(p0 + 1) * OP + o] = y1;
                lsum += y0 + y1;
                lsq  += y0 * y0 + y1 * y1;
            }
        }
    }

    // ---- per-tree LayerNorm over O*128 values (ddof=1 std) ----
#pragma unroll
    for (int off = 16; off; off >>= 1) {
        lsum += __shfl_xor_sync(0xffffffffu, lsum, off);
        lsq  += __shfl_xor_sync(0xffffffffu, lsq,  off);
    }
    const int wid = tid >> 5, lane = tid & 31;
    if (lane == 0) { sm->red[wid] = lsum; sm->red[8 + wid] = lsq; }
    __syncthreads();
    if (tid == 0) {
        float s = 0.f, q = 0.f;
        for (int w = 0; w < 8; ++w) { s += sm->red[w]; q += sm->red[8 + w]; }
        const float n = (float)(O * 128);
        float mean = s / n;
        float var = (q - n * mean * mean) / (n - 1.f);
        var = fmaxf(var, 0.f);
        float inv = 1.f / (sqrtf(var) + 1e-5f);
        sm->red[16] = mean;
        sm->red[17] = inv;
    }
    __syncthreads();
    const float mean = sm->red[16];
    const float inv  = sm->red[17];
    // normalize valid region [128][O] (pitch OP): half a row per thread, float4
    {
        constexpr int HALF = O / 2;
        float4* p4 = (float4*)(act_out + (tid >> 1) * OP + (tid & 1) * HALF);
#pragma unroll 4
        for (int i = 0; i < HALF / 4; ++i) {
            float4 f = p4[i];
            f.x = (f.x - mean) * inv;
            f.y = (f.y - mean) * inv;
            f.z = (f.z - mean) * inv;
            f.w = (f.w - mean) * inv;
            if (LEAKY) {
                if (f.x < 0.f) f.x *= 0.01f;
                if (f.y < 0.f) f.y *= 0.01f;
                if (f.z < 0.f) f.z *= 0.01f;
                if (f.w < 0.f) f.w *= 0.01f;
            }
            p4[i] = f;
        }
    }
    __syncthreads();
}

// ---------------------------------------------------------------------------
// Weight transpose pre-pass: Wt[(k*C+c)*O + o] = W[o*C*3 + c*3 + k]
// ---------------------------------------------------------------------------
__global__ void wtrans_all(const float* __restrict__ W1,
                           const float* __restrict__ W2,
                           const float* __restrict__ W3)
{
    int i = blockIdx.x * 256 + threadIdx.x;
    if (i < 98304) {                       // W1: O=256, C=128
        const int O = 256, C = 128;
        int o = i % O, t = i / O, c = t % C, k = t / C;
        g_Wt1[i] = W1[(o * C + c) * 3 + k];
    } else if (i < 196608) {               // W2: O=128, C=256
        int j = i - 98304;
        const int O = 128, C = 256;
        int o = j % O, t = j / O, c = t % C, k = t / C;
        g_Wt2[j] = W2[(o * C + c) * 3 + k];
    } else if (i < 221184) {               // W3: O=64, C=128
        int j = i - 196608;
        const int O = 64, C = 128;
        int o = j % O, t = j / O, c = t % C, k = t / C;
        g_Wt3[j] = W3[(o * C + c) * 3 + k];
    }
}

// ---------------------------------------------------------------------------
// Main fused kernel: one CTA per tree.
// ---------------------------------------------------------------------------
__global__ void __launch_bounds__(256, 1)
bao_main(const float* __restrict__ trees,
         const int* __restrict__ indexes,
         const float* __restrict__ b1,
         const float* __restrict__ b2,
         const float* __restrict__ b3,
         const float* __restrict__ W4,
         const float* __restrict__ b4,
         const float* __restrict__ W5,
         const float* __restrict__ b5,
         float* __restrict__ outp)
{
    extern __shared__ char smem_raw[];
    SmemT* sm = (SmemT*)smem_raw;
    const int b = blockIdx.x;
    const int tid = threadIdx.x;

    // load tree [128c][128n] -> transposed smem bufB[n][c] (pitch 132)
    {
        const float* src = trees + (size_t)b * 16384;
#pragma unroll
        for (int it = 0; it < 64; ++it) {
            int i = it * 256 + tid;        // coalesced gmem read
            int c = i >> 7, n = i & 127;
            sm->bufB[n * 132 + c] = src[i];
        }
    }
    for (int i = tid; i < 381; i += 256) sm->idx[i] = indexes[(size_t)b * 381 + i];
    __syncthreads();

    // per-thread gather row indices for positions p = tm*8 + j
    const int tm = tid >> 4;
    int I[24];
#pragma unroll
    for (int k = 0; k < 3; ++k)
#pragma unroll
        for (int j = 0; j < 8; ++j) {
            int p = tm * 8 + j;
            I[k * 8 + j] = (p == 0) ? 0 : sm->idx[3 * (p - 1) + k];
        }

    layer<128, 132, 256, 260, true >(sm->bufB, sm->bufA, g_Wt1, b1, sm, tid, I);
    layer<256, 260, 128, 132, true >(sm->bufA, sm->bufB, g_Wt2, b2, sm, tid, I);
    layer<128, 132,  64,  68, false>(sm->bufB, sm->bufA, g_Wt3, b3, sm, tid, I);

    // DynamicPooling: max over positions -> red[0..63]  (layer3 out pitch 68)
    if (tid < 64) {
        float m = sm->bufA[tid];
#pragma unroll 8
        for (int p = 1; p < 128; ++p) m = fmaxf(m, sm->bufA[p * 68 + tid]);
        sm->red[tid] = m;
    }
    __syncthreads();

    // FC 64->32 (leaky) -> 32->1
    if (tid < 32) {
        float h = b4[tid];
#pragma unroll 8
        for (int j = 0; j < 64; ++j) h += W4[tid * 64 + j] * sm->red[j];
        if (h < 0.f) h *= 0.01f;
        float contrib = W5[tid] * h;
#pragma unroll
        for (int off = 16; off; off >>= 1)
            contrib += __shfl_xor_sync(0xffffffffu, contrib, off);
        if (tid == 0) outp[b] = contrib + b5[0];
    }
}

// ---------------------------------------------------------------------------
// Launch
// ---------------------------------------------------------------------------
extern "C" void kernel_launch(void* const* d_in, const int* in_sizes, int n_in,
                              void* d_out, int out_size)
{
    const float *trees, *W1, *b1, *W2, *b2, *W3, *b3, *W4, *b4, *W5, *b5;
    const int* indexes;

    if (in_sizes[0] == 33554432 && n_in >= 12 && in_sizes[1] == 780288) {
        // setup_inputs dict order: trees, indexes, W1,b1, ..., W5,b5
        trees   = (const float*)d_in[0];
        indexes = (const int*)  d_in[1];
        W1 = (const float*)d_in[2];  b1 = (const float*)d_in[3];
        W2 = (const float*)d_in[4];  b2 = (const float*)d_in[5];
        W3 = (const float*)d_in[6];  b3 = (const float*)d_in[7];
        W4 = (const float*)d_in[8];  b4 = (const float*)d_in[9];
        W5 = (const float*)d_in[10]; b5 = (const float*)d_in[11];
    } else if (in_sizes[0] == 33554432) {
        // reference() arg order: trees, W1,b1, ..., W5,b5, indexes
        trees = (const float*)d_in[0];
        W1 = (const float*)d_in[1];  b1 = (const float*)d_in[2];
        W2 = (const float*)d_in[3];  b2 = (const float*)d_in[4];
        W3 = (const float*)d_in[5];  b3 = (const float*)d_in[6];
        W4 = (const float*)d_in[7];  b4 = (const float*)d_in[8];
        W5 = (const float*)d_in[9];  b5 = (const float*)d_in[10];
        indexes = (const int*)d_in[11];
    } else {
        // alphabetical order: W1..W5, b1..b5, indexes, trees
        W1 = (const float*)d_in[0];  W2 = (const float*)d_in[1];
        W3 = (const float*)d_in[2];  W4 = (const float*)d_in[3];
        W5 = (const float*)d_in[4];
        b1 = (const float*)d_in[5];  b2 = (const float*)d_in[6];
        b3 = (const float*)d_in[7];  b4 = (const float*)d_in[8];
        b5 = (const float*)d_in[9];
        indexes = (const int*)  d_in[10];
        trees   = (const float*)d_in[11];
    }

    wtrans_all<<<(221184 + 255) / 256, 256>>>(W1, W2, W3);

    const int smem_bytes = (int)sizeof(SmemT);
    cudaFuncSetAttribute(bao_main, cudaFuncAttributeMaxDynamicSharedMemorySize,
                         smem_bytes);
    bao_main<<<2048, 256, smem_bytes>>>(trees, indexes, b1, b2, b3,
                                        W4, b4, W5, b5, (float*)d_out);
}

// round 5
// speedup vs baseline: 1.6471x; 1.6471x over previous
#include <cuda_runtime.h>

typedef unsigned long long ull;

// ---------------------------------------------------------------------------
// B=2048 trees, N=128 nodes, M=127 conv positions.
// Channels: 128 -> 256 -> 128 -> 64, then FC 64->32->1.
//
// f32x2 packing axis = CHANNEL PARITY:
//   acc lanes = (even-c partial, odd-c partial), summed in epilogue.
//   activation pair (act[c], act[c+1]) = adjacent floats in [pos][C] smem
//     -> direct lane of an LDS.128 (ulonglong2), no packing MOVs.
//   weight pair (W[c][o], W[c+1][o]) pre-paired in a gmem prepass.
//
// Thread map: to = tid&15 (16 o-lanes), tm = tid>>4 (16 pos-groups of 8).
//   Gather LDS: 16-lane broadcast (conflict-free).
//   Weight LDS.64: 16 consecutive ulls per 16 lanes (conflict-free).
// ---------------------------------------------------------------------------

// Pre-paired weights: g_Wp[(k*(C/2) + cp)*O + o] = (W[o][2cp][k], W[o][2cp+1][k])
__device__ ull g_W1p[3 * 64 * 256];    // 768 KB total across the three
__device__ ull g_W2p[3 * 128 * 128];
__device__ ull g_W3p[3 * 64 * 64];

struct SmemT {
    float bufA[128 * 260];   // 133,120 B : [pos][260]
    float bufB[128 * 132];   //  67,584 B : [pos][132]
    ull   wbuf[2 * 512];     //   8,192 B : double-buffered weight stage
    int   idx[384];
    float red[80];
};                           // ~210.8 KB

__device__ __forceinline__ ull pk(float lo, float hi) {
    ull r;
    asm("mov.b64 %0, {%1,%2};" : "=l"(r) : "f"(lo), "f"(hi));
    return r;
}
__device__ __forceinline__ void unpk(ull x, float& lo, float& hi) {
    asm("mov.b64 {%0,%1}, %2;" : "=f"(lo), "=f"(hi) : "l"(x));
}
// packed fp32x2 FMA: d = a*b + d (lanewise)
__device__ __forceinline__ void ffma2(ull& d, ull a, ull b) {
    asm("fma.rn.f32x2 %0, %1, %2, %0;" : "+l"(d) : "l"(a), "l"(b));
}

// ---------------------------------------------------------------------------
// One tree-conv layer + per-tree LayerNorm (+ optional leaky ReLU).
//   act_in : [128][CP] smem (valid cols [0,C)), act_out : [128][OP]
//   Wg     : pre-paired weights, [(k*C/2 + cp)*O + o]
//   I      : gather rows I[k*8+j] for positions p = tm*8+j
// ---------------------------------------------------------------------------
template <int C, int CP, int O, int OP, bool LEAKY>
__device__ void layer(const float* __restrict__ act_in,
                      float* __restrict__ act_out,
                      const ull* __restrict__ Wg,
                      const float* __restrict__ bias,
                      SmemT* sm, int tid, const int* I)
{
    constexpr int OT = 64;            // o-tile per pass
    constexpr int RO = 4;             // o's per thread
    constexpr int PASSES = O / OT;
    constexpr int NB = C / 16;        // 16-channel blocks per k
    constexpr int T = 3 * NB;         // blocks per pass (always even)

    const int to = tid & 15;
    const int tm = tid >> 4;
    const int s0 = tid >> 6;          // staging row for element e0 = tid
    const int o0 = tid & 63;

    float lsum = 0.f, lsq = 0.f;

    for (int pass = 0; pass < PASSES; ++pass) {
        const int ob = pass * OT;

        ull acc[RO][8];
#pragma unroll
        for (int r = 0; r < RO; ++r)
#pragma unroll
            for (int j = 0; j < 8; ++j) acc[r][j] = 0ull;

        // prefetch staging regs for block t=0 (k=0, cp base 0)
        ull pw0 = Wg[(size_t)s0 * O + ob + o0];
        ull pw1 = Wg[(size_t)(s0 + 4) * O + ob + o0];

        for (int t = 0; t < T; ++t) {
            const int k  = t / NB;
            const int cb = (t % NB) * 16;

            ull* wb = sm->wbuf + (t & 1) * 512;
            wb[tid]       = pw0;
            wb[tid + 256] = pw1;
            __syncthreads();

            if (t + 1 < T) {
                const int k2   = (t + 1) / NB;
                const int cbp2 = ((t + 1) % NB) * 8;
                const int base = k2 * (C / 2) + cbp2;
                pw0 = Wg[(size_t)(base + s0) * O + ob + o0];
                pw1 = Wg[(size_t)(base + s0 + 4) * O + ob + o0];
            }

            const float* ab[8];
#pragma unroll
            for (int j = 0; j < 8; ++j)
                ab[j] = act_in + I[k * 8 + j] * CP + cb;

#pragma unroll
            for (int sg = 0; sg < 4; ++sg) {
                // 4 channels (2 pairs) per position: one LDS.128 each
                ulonglong2 v[8];
#pragma unroll
                for (int j = 0; j < 8; ++j)
                    v[j] = *(const ulonglong2*)(ab[j] + sg * 4);

                const ull* wr = wb + sg * 128 + to;
                ull w0[RO], w1[RO];
#pragma unroll
                for (int r = 0; r < RO; ++r) {
                    w0[r] = wr[r * 16];        // c-pair sg*2
                    w1[r] = wr[64 + r * 16];   // c-pair sg*2+1
                }

#pragma unroll
                for (int r = 0; r < RO; ++r)
#pragma unroll
                    for (int j = 0; j < 8; ++j)
                        ffma2(acc[r][j], w0[r], v[j].x);
#pragma unroll
                for (int r = 0; r < RO; ++r)
#pragma unroll
                    for (int j = 0; j < 8; ++j)
                        ffma2(acc[r][j], w1[r], v[j].y);
            }
        }

        // ---- epilogue: lanes sum + bias, zero slot 0, write, LN stats ----
#pragma unroll
        for (int r = 0; r < RO; ++r) {
            const int o = ob + to + r * 16;
            const float bo = __ldg(bias + o);
#pragma unroll
            for (int j = 0; j < 8; ++j) {
                float lo, hi;
                unpk(acc[r][j], lo, hi);
                float y = lo + hi + bo;
                const int p = tm * 8 + j;
                if (p == 0) y = 0.f;
                act_out[p * OP + o] = y;
                lsum += y;
                lsq  += y * y;
            }
        }
    }

    // ---- per-tree LayerNorm over O*128 values (ddof=1 std) ----
#pragma unroll
    for (int off = 16; off; off >>= 1) {
        lsum += __shfl_xor_sync(0xffffffffu, lsum, off);
        lsq  += __shfl_xor_sync(0xffffffffu, lsq,  off);
    }
    const int wid = tid >> 5, lane = tid & 31;
    if (lane == 0) { sm->red[wid] = lsum; sm->red[8 + wid] = lsq; }
    __syncthreads();
    if (tid == 0) {
        float s = 0.f, q = 0.f;
        for (int w = 0; w < 8; ++w) { s += sm->red[w]; q += sm->red[8 + w]; }
        const float n = (float)(O * 128);
        float mean = s / n;
        float var = (q - n * mean * mean) / (n - 1.f);
        var = fmaxf(var, 0.f);
        float inv = 1.f / (sqrtf(var) + 1e-5f);
        sm->red[16] = mean;
        sm->red[17] = inv;
    }
    __syncthreads();
    const float mean = sm->red[16];
    const float inv  = sm->red[17];
    {
        constexpr int HALF = O / 2;
        float4* p4 = (float4*)(act_out + (tid >> 1) * OP + (tid & 1) * HALF);
#pragma unroll 4
        for (int i = 0; i < HALF / 4; ++i) {
            float4 f = p4[i];
            f.x = (f.x - mean) * inv;
            f.y = (f.y - mean) * inv;
            f.z = (f.z - mean) * inv;
            f.w = (f.w - mean) * inv;
            if (LEAKY) {
                if (f.x < 0.f) f.x *= 0.01f;
                if (f.y < 0.f) f.y *= 0.01f;
                if (f.z < 0.f) f.z *= 0.01f;
                if (f.w < 0.f) f.w *= 0.01f;
            }
            p4[i] = f;
        }
    }
    __syncthreads();
}

// ---------------------------------------------------------------------------
// Weight prepass: pair channels.  g[(k*CH + cp)*O + o] = (W[o][2cp][k], W[o][2cp+1][k])
// ---------------------------------------------------------------------------
__global__ void wprep(const float* __restrict__ W1,
                      const float* __restrict__ W2,
                      const float* __restrict__ W3)
{
    int i = blockIdx.x * 256 + threadIdx.x;
    if (i < 49152) {                        // L1: O=256, C=128 (CH=64)
        int o = i & 255, t = i >> 8, cp = t & 63, k = t >> 6;
        g_W1p[i] = pk(W1[(o * 128 + 2 * cp) * 3 + k],
                      W1[(o * 128 + 2 * cp + 1) * 3 + k]);
    } else if (i < 98304) {                 // L2: O=128, C=256 (CH=128)
        int j = i - 49152;
        int o = j & 127, t = j >> 7, cp = t & 127, k = t >> 7;
        g_W2p[j] = pk(W2[(o * 256 + 2 * cp) * 3 + k],
                      W2[(o * 256 + 2 * cp + 1) * 3 + k]);
    } else if (i < 110592) {                // L3: O=64, C=128 (CH=64)
        int j = i - 98304;
        int o = j & 63, t = j >> 6, cp = t & 63, k = t >> 6;
        g_W3p[j] = pk(W3[(o * 128 + 2 * cp) * 3 + k],
                      W3[(o * 128 + 2 * cp + 1) * 3 + k]);
    }
}

// ---------------------------------------------------------------------------
// Main fused kernel: one CTA per tree.
// ---------------------------------------------------------------------------
__global__ void __launch_bounds__(256, 1)
bao_main(const float* __restrict__ trees,
         const int* __restrict__ indexes,
         const float* __restrict__ b1,
         const float* __restrict__ b2,
         const float* __restrict__ b3,
         const float* __restrict__ W4,
         const float* __restrict__ b4,
         const float* __restrict__ W5,
         const float* __restrict__ b5,
         float* __restrict__ outp)
{
    extern __shared__ char smem_raw[];
    SmemT* sm = (SmemT*)smem_raw;
    const int b = blockIdx.x;
    const int tid = threadIdx.x;

    // load tree [128c][128n] -> transposed smem bufB[n][c] (pitch 132)
    {
        const float* src = trees + (size_t)b * 16384;
#pragma unroll
        for (int it = 0; it < 64; ++it) {
            int i = it * 256 + tid;            // coalesced gmem read
            int c = i >> 7, n = i & 127;
            sm->bufB[n * 132 + c] = src[i];
        }
    }
    for (int i = tid; i < 381; i += 256) sm->idx[i] = indexes[(size_t)b * 381 + i];
    __syncthreads();

    // per-thread gather rows for positions p = tm*8 + j
    const int tm = tid >> 4;
    int I[24];
#pragma unroll
    for (int k = 0; k < 3; ++k)
#pragma unroll
        for (int j = 0; j < 8; ++j) {
            int p = tm * 8 + j;
            I[k * 8 + j] = (p == 0) ? 0 : sm->idx[3 * (p - 1) + k];
        }

    layer<128, 132, 256, 260, true >(sm->bufB, sm->bufA, g_W1p, b1, sm, tid, I);
    layer<256, 260, 128, 132, true >(sm->bufA, sm->bufB, g_W2p, b2, sm, tid, I);
    layer<128, 132,  64,  68, false>(sm->bufB, sm->bufA, g_W3p, b3, sm, tid, I);

    // DynamicPooling: max over positions (layer3 out pitch 68)
    if (tid < 64) {
        float m = sm->bufA[tid];
#pragma unroll 8
        for (int p = 1; p < 128; ++p) m = fmaxf(m, sm->bufA[p * 68 + tid]);
        sm->red[tid] = m;
    }
    __syncthreads();

    // FC 64->32 (leaky) -> 32->1
    if (tid < 32) {
        float h = b4[tid];
#pragma unroll 8
        for (int j = 0; j < 64; ++j) h += W4[tid * 64 + j] * sm->red[j];
        if (h < 0.f) h *= 0.01f;
        float contrib = W5[tid] * h;
#pragma unroll
        for (int off = 16; off; off >>= 1)
            contrib += __shfl_xor_sync(0xffffffffu, contrib, off);
        if (tid == 0) outp[b] = contrib + b5[0];
    }
}

// ---------------------------------------------------------------------------
// Launch
// ---------------------------------------------------------------------------
extern "C" void kernel_launch(void* const* d_in, const int* in_sizes, int n_in,
                              void* d_out, int out_size)
{
    const float *trees, *W1, *b1, *W2, *b2, *W3, *b3, *W4, *b4, *W5, *b5;
    const int* indexes;

    if (in_sizes[0] == 33554432 && n_in >= 12 && in_sizes[1] == 780288) {
        // setup_inputs dict order: trees, indexes, W1,b1, ..., W5,b5
        trees   = (const float*)d_in[0];
        indexes = (const int*)  d_in[1];
        W1 = (const float*)d_in[2];  b1 = (const float*)d_in[3];
        W2 = (const float*)d_in[4];  b2 = (const float*)d_in[5];
        W3 = (const float*)d_in[6];  b3 = (const float*)d_in[7];
        W4 = (const float*)d_in[8];  b4 = (const float*)d_in[9];
        W5 = (const float*)d_in[10]; b5 = (const float*)d_in[11];
    } else if (in_sizes[0] == 33554432) {
        // reference() arg order: trees, W1,b1, ..., W5,b5, indexes
        trees = (const float*)d_in[0];
        W1 = (const float*)d_in[1];  b1 = (const float*)d_in[2];
        W2 = (const float*)d_in[3];  b2 = (const float*)d_in[4];
        W3 = (const float*)d_in[5];  b3 = (const float*)d_in[6];
        W4 = (const float*)d_in[7];  b4 = (const float*)d_in[8];
        W5 = (const float*)d_in[9];  b5 = (const float*)d_in[10];
        indexes = (const int*)d_in[11];
    } else {
        // alphabetical order: W1..W5, b1..b5, indexes, trees
        W1 = (const float*)d_in[0];  W2 = (const float*)d_in[1];
        W3 = (const float*)d_in[2];  W4 = (const float*)d_in[3];
        W5 = (const float*)d_in[4];
        b1 = (const float*)d_in[5];  b2 = (const float*)d_in[6];
        b3 = (const float*)d_in[7];  b4 = (const float*)d_in[8];
        b5 = (const float*)d_in[9];
        indexes = (const int*)  d_in[10];
        trees   = (const float*)d_in[11];
    }

    // 1) pair-pack weights
    wprep<<<(110592 + 255) / 256, 256>>>(W1, W2, W3);

    // 2) fused per-tree pipeline
    const int smem_bytes = (int)sizeof(SmemT);
    cudaFuncSetAttribute(bao_main, cudaFuncAttributeMaxDynamicSharedMemorySize,
                         smem_bytes);
    bao_main<<<2048, 256, smem_bytes>>>(trees, indexes, b1, b2, b3,
                                        W4, b4, W5, b5, (float*)d_out);
}